// round 15
// baseline (speedup 1.0000x reference)
#include <cuda_runtime.h>
#include <cuda_bf16.h>
#include <cstdint>

#define T_STEPS 2048
#define B_SZ    32
#define D_SZ    512
#define H_SZ    512
#define G_SZ    2048
#define NBLK    128
#define NGRP    4
#define GRP_B   8       // batch elements per group
#define GBLK    32      // blocks per group

// ---------------- device scratch ----------------
__device__ float g_xproj[(size_t)T_STEPS * G_SZ * B_SZ];     // [T][4H][B]
// m packed bf16 pairs: P[buf][grp][kp 256][b 8], uint32 = (m[2kp], m[2kp+1])
__device__ uint32_t g_mP_hi[2 * NGRP * 256 * GRP_B];
__device__ uint32_t g_mP_lo[2 * NGRP * 256 * GRP_B];
__device__ int g_bars[NGRP * 32];    // counter per group at [grp*32]

// ---------------- helpers ----------------
#define CP_ASYNC16(dst_u32, src_ptr) \
    asm volatile("cp.async.cg.shared.global [%0], [%1], 16;\n" :: "r"(dst_u32), "l"(src_ptr))
#define CP_COMMIT() asm volatile("cp.async.commit_group;\n")
#define CP_WAIT(N)  asm volatile("cp.async.wait_group %0;\n" :: "n"(N))

__device__ __forceinline__ void mma_bf16(float& d0, float& d1, float& d2, float& d3,
                                         uint32_t a0, uint32_t a1, uint32_t a2, uint32_t a3,
                                         uint32_t b0, uint32_t b1) {
    asm volatile(
        "mma.sync.aligned.m16n8k16.row.col.f32.bf16.bf16.f32 "
        "{%0,%1,%2,%3},{%4,%5,%6,%7},{%8,%9},{%0,%1,%2,%3};"
        : "+f"(d0), "+f"(d1), "+f"(d2), "+f"(d3)
        : "r"(a0), "r"(a1), "r"(a2), "r"(a3), "r"(b0), "r"(b1));
}
__device__ __forceinline__ uint32_t pack_bf2(float a, float b) {
    __nv_bfloat162 t = __floats2bfloat162_rn(a, b);   // a -> low half
    return *(uint32_t*)&t;
}
__device__ __forceinline__ void split_pair(float f0, float f1, uint32_t& hi, uint32_t& lo) {
    float h0 = __bfloat162float(__float2bfloat16_rn(f0));
    float h1 = __bfloat162float(__float2bfloat16_rn(f1));
    hi = pack_bf2(h0, h1);
    lo = pack_bf2(f0 - h0, f1 - h1);
}

// ============ phase 1: x_proj GEMM (bf16-pair 3-mma k16, 3-stage) ============
#define XPA 2304
#define XPB 4352
#define XP_SMEM_FL (3 * (XPA + XPB))

__global__ __launch_bounds__(256, 2) void xproj_gemm(
    const float* __restrict__ A, const float* __restrict__ Bm,
    const float* __restrict__ bias)
{
    extern __shared__ float sm[];
    float* As = sm;
    float* Bs = sm + 3 * XPA;
    float* stage = Bs;

    const unsigned as_u32 = (unsigned)__cvta_generic_to_shared(As);
    const unsigned bs_u32 = (unsigned)__cvta_generic_to_shared(Bs);

    const int tid = threadIdx.x;

    if (blockIdx.x == 0 && blockIdx.y == 0) {   // fold reset
        for (int i = tid; i < NGRP * 32; i += 256) g_bars[i] = 0;
        for (int i = tid; i < 2 * NGRP * 256 * GRP_B; i += 256) { g_mP_hi[i] = 0u; g_mP_lo[i] = 0u; }
    }

    const int n0 = blockIdx.x * 128;
    const int m0 = blockIdx.y * 64;
    const int w   = tid >> 5;
    const int l   = tid & 31;
    const int gid = l >> 2;
    const int tig = l & 3;
    const int nw  = w * 16;

    auto issue = [&](int it, int buf) {
        const int kc = it * 32;
#pragma unroll
        for (int i = 0; i < 2; i++) {
            int idx = tid + i * 256;
            int m = idx >> 3, kq = (idx & 7) << 2;
            CP_ASYNC16(as_u32 + (unsigned)((buf * XPA + m * 36 + kq) * 4),
                       A + (size_t)(m0 + m) * D_SZ + kc + kq);
        }
#pragma unroll
        for (int i = 0; i < 4; i++) {
            int idx = tid + i * 256;
            int k = idx >> 5, nq = (idx & 31) << 2;
            CP_ASYNC16(bs_u32 + (unsigned)((buf * XPB + k * 136 + nq) * 4),
                       Bm + (size_t)(kc + k) * G_SZ + n0 + nq);
        }
        CP_COMMIT();
    };

    float acc[4][2][4];
#pragma unroll
    for (int mt = 0; mt < 4; mt++)
#pragma unroll
        for (int nt = 0; nt < 2; nt++)
#pragma unroll
            for (int r = 0; r < 4; r++) acc[mt][nt][r] = 0.0f;

    issue(0, 0);
    issue(1, 1);

#pragma unroll 1
    for (int it = 0; it < 16; it++) {
        if (it < 15) { CP_WAIT(1); } else { CP_WAIT(0); }
        __syncthreads();
        if (it + 2 < 16) issue(it + 2, (it + 2) % 3);

        const float* Ab = As + (it % 3) * XPA;
        const float* Bb = Bs + (it % 3) * XPB;

#pragma unroll
        for (int c = 0; c < 2; c++) {
            const int k0 = c * 16 + tig * 2;
            uint32_t bh[2][2], bl[2][2];
#pragma unroll
            for (int nt = 0; nt < 2; nt++) {
                const int n = nw + nt * 8 + gid;
                float b00 = Bb[k0 * 136 + n];
                float b01 = Bb[(k0 + 1) * 136 + n];
                float b10 = Bb[(k0 + 8) * 136 + n];
                float b11 = Bb[(k0 + 9) * 136 + n];
                split_pair(b00, b01, bh[nt][0], bl[nt][0]);
                split_pair(b10, b11, bh[nt][1], bl[nt][1]);
            }
#pragma unroll
            for (int mt = 0; mt < 4; mt++) {
                const int row0 = mt * 16 + gid;
                float2 f0 = *(const float2*)&Ab[row0 * 36 + k0];
                float2 f1 = *(const float2*)&Ab[(row0 + 8) * 36 + k0];
                float2 f2 = *(const float2*)&Ab[row0 * 36 + k0 + 8];
                float2 f3 = *(const float2*)&Ab[(row0 + 8) * 36 + k0 + 8];
                uint32_t ah0, al0, ah1, al1, ah2, al2, ah3, al3;
                split_pair(f0.x, f0.y, ah0, al0);
                split_pair(f1.x, f1.y, ah1, al1);
                split_pair(f2.x, f2.y, ah2, al2);
                split_pair(f3.x, f3.y, ah3, al3);
#pragma unroll
                for (int nt = 0; nt < 2; nt++) {
                    mma_bf16(acc[mt][nt][0], acc[mt][nt][1], acc[mt][nt][2], acc[mt][nt][3],
                             ah0, ah1, ah2, ah3, bh[nt][0], bh[nt][1]);
                    mma_bf16(acc[mt][nt][0], acc[mt][nt][1], acc[mt][nt][2], acc[mt][nt][3],
                             ah0, ah1, ah2, ah3, bl[nt][0], bl[nt][1]);
                    mma_bf16(acc[mt][nt][0], acc[mt][nt][1], acc[mt][nt][2], acc[mt][nt][3],
                             al0, al1, al2, al3, bh[nt][0], bh[nt][1]);
                }
            }
        }
    }
    __syncthreads();

#pragma unroll
    for (int mt = 0; mt < 4; mt++)
#pragma unroll
        for (int nt = 0; nt < 2; nt++) {
            int m = mt * 16 + gid;
            int n = nw + nt * 8 + tig * 2;
            stage[n * 68 + m]           = acc[mt][nt][0];
            stage[(n + 1) * 68 + m]     = acc[mt][nt][1];
            stage[n * 68 + m + 8]       = acc[mt][nt][2];
            stage[(n + 1) * 68 + m + 8] = acc[mt][nt][3];
        }
    __syncthreads();

#pragma unroll
    for (int i = 0; i < 8; i++) {
        int idx = tid + i * 256;
        int n = idx >> 4, mq = (idx & 15) << 2;
        float4 v = *(float4*)&stage[n * 68 + mq];
        float bb = bias[n0 + n];
        v.x += bb; v.y += bb; v.z += bb; v.w += bb;
        int mg = m0 + mq;
        int t = mg >> 5, b = mg & 31;
        *(float4*)&g_xproj[((size_t)t * G_SZ + n0 + n) * B_SZ + b] = v;
    }
}

// ============ phase 2: four independent 32-block group recurrences ==========
// grp = bid>>5 owns b [grp*8, +8); block owns 16 h (64 gate cols). K-split 16.
// mma role-swap: A = W (M=16 cc per tile, 4 tiles), B = m (k16 x n8 batch).
#define MPS8 12                                     // u32 stride per kp row
#define MHI_OFF_B 0                                 // 256*12*4 = 12288
#define MLO_OFF_B 12288
#define RED_OFF_B 24576                             // [16w][64cc][12] f32 = 49152
#define XP_OFF_B  73728                             // [2][64cc][8b] f32 = 4096
#define PAD_OFF_B 77824                             // [2][8] f32 = 64 (pad 128)
#define M2F_OFF_B 77952                             // [16h][8b] f32 = 512
#define SMEM_BYTES_L 78464

__device__ __forceinline__ float fsig(float x)  { return 1.0f / (1.0f + __expf(-x)); }
__device__ __forceinline__ float ftanh(float x) { return 1.0f - 2.0f / (__expf(2.0f * x) + 1.0f); }

__global__ __launch_bounds__(512, 1) void lstm_kernel(
    const float* __restrict__ paddings,
    const float* __restrict__ W_h,
    float* __restrict__ out,
    int write_final)
{
    extern __shared__ char smc[];
    const uint32_t* mhi_s = (const uint32_t*)(smc + MHI_OFF_B);
    const uint32_t* mlo_s = (const uint32_t*)(smc + MLO_OFF_B);
    float* red   = (float*)(smc + RED_OFF_B);
    float* xp_s  = (float*)(smc + XP_OFF_B);
    float* pad_s = (float*)(smc + PAD_OFF_B);
    float* m2f_s = (float*)(smc + M2F_OFF_B);

    const unsigned smem_u32 = (unsigned)__cvta_generic_to_shared(smc);
    const unsigned mhi_u32  = smem_u32 + MHI_OFF_B;
    const unsigned mlo_u32  = smem_u32 + MLO_OFF_B;
    const unsigned xp_u32   = smem_u32 + XP_OFF_B;
    const unsigned pad_u32  = smem_u32 + PAD_OFF_B;

    const int tid  = threadIdx.x;
    const int bid  = blockIdx.x;
    const int grp  = bid >> 5;
    const int gbid = bid & 31;
    const int h_base = gbid * 16;

    const int l   = tid & 31;
    const int w   = tid >> 5;
    const int gid = l >> 2;
    const int tig = l & 3;

    // ---- W fragments as A (m16 row-major), bf16 pairs in registers ----
    // chunk J, tile ct: a_r holds W pair (k, k+1) at cc:
    //   r0: cc = ct*16+gid,   k = w*32 + J*16 + tig*2
    //   r1: cc = ct*16+gid+8, same k
    //   r2: cc = ct*16+gid,   k + 8
    //   r3: cc = ct*16+gid+8, k + 8
    uint32_t Wh[2][4][4], Wl[2][4][4];
#pragma unroll
    for (int J = 0; J < 2; J++)
#pragma unroll
        for (int ct = 0; ct < 4; ct++)
#pragma unroll
            for (int r = 0; r < 4; r++) {
                int cc = ct * 16 + gid + ((r & 1) ? 8 : 0);
                int k  = w * 32 + J * 16 + tig * 2 + ((r >> 1) ? 8 : 0);
                int g  = cc & 3;
                int j  = cc >> 2;             // 0..15
                const float* wp = W_h + (size_t)g * H_SZ + h_base + j;
                float w0 = wp[(size_t)k * G_SZ];
                float w1 = wp[(size_t)(k + 1) * G_SZ];
                split_pair(w0, w1, Wh[J][ct][r], Wl[J][ct][r]);
            }

    // cell ownership (tid<128): cb = tid&7, cj = tid>>3 (0..15)
    const int cb  = tid & 7;
    const int cj  = tid >> 3;
    const int h_o = h_base + cj;
    const int b_g = grp * GRP_B + cb;

    // xp loader (tid<128): 64cc x 8b = 128 granules; xcc = tid>>1, xq = (tid&1)*4
    const int xcc = tid >> 1;
    const int xq  = (tid & 1) << 2;
    const float* xp_src_base = g_xproj +
        ((size_t)((xcc & 3) * H_SZ + h_base + (xcc >> 2))) * B_SZ + grp * GRP_B + xq;

    // m loader: per chunk J, plane p = l>>4 (0 hi, 1 lo); lane covers
    // kp = w*16 + J*8 + ((l&15)>>1), granule (l&1)
    const int ml    = l & 15;
    const int mplane = l >> 4;
    const int mrow  = ml >> 1;
    const int mq16  = (ml & 1) * 16;

    // prologue: xp(0) + pad(0)
    if (tid < 128)
        CP_ASYNC16(xp_u32 + (unsigned)((xcc * GRP_B + xq) * 4), xp_src_base);
    if (tid >= 128 && tid < 130)
        CP_ASYNC16(pad_u32 + (unsigned)((tid - 128) * 16),
                   paddings + grp * GRP_B + (tid - 128) * 4);
    CP_COMMIT();

    float c_reg = 0.0f, m_prev = 0.0f;
    int* my_bar = &g_bars[grp * 32];

#pragma unroll 1
    for (int s = 0; s < T_STEPS; s++) {
        const int pb = s & 1, nb = pb ^ 1;
        const char* srcP_hi = (const char*)(g_mP_hi + (pb * NGRP + grp) * 256 * GRP_B);
        const char* srcP_lo = (const char*)(g_mP_lo + (pb * NGRP + grp) * 256 * GRP_B);

        // ---- 2 warp-private m groups: each lane loads one 16B granule ----
#pragma unroll
        for (int J = 0; J < 2; J++) {
            const int kp = w * 16 + J * 8 + mrow;
            const char* src = (mplane ? srcP_lo : srcP_hi) + kp * 32 + mq16;
            const unsigned dst = (mplane ? mlo_u32 : mhi_u32)
                               + (unsigned)(kp * (MPS8 * 4) + mq16);
            CP_ASYNC16(dst, src);
            CP_COMMIT();
        }
        // ---- xp(s+1)+pad(s+1) prefetch ----
        if (s + 1 < T_STEPS) {
            if (tid < 128)
                CP_ASYNC16(xp_u32 + (unsigned)(((nb * 512) + xcc * GRP_B + xq) * 4),
                           xp_src_base + (size_t)(s + 1) * G_SZ * B_SZ);
            if (tid >= 128 && tid < 130)
                CP_ASYNC16(pad_u32 + (unsigned)((nb * 8 + (tid - 128) * 4) * 4),
                           paddings + (size_t)(s + 1) * B_SZ + grp * GRP_B + (tid - 128) * 4);
        }
        CP_COMMIT();

        float acc[4][4];
#pragma unroll
        for (int ct = 0; ct < 4; ct++)
#pragma unroll
            for (int r = 0; r < 4; r++) acc[ct][r] = 0.0f;

        // ---- 2 mma chunks, warp-paced: B = m frags, A = W regs ----
#define MMA_CHUNK(J, WN)                                                           \
        {                                                                          \
            CP_WAIT(WN);                                                           \
            __syncwarp();                                                          \
            const int i0 = (w * 16 + (J) * 8 + tig) * MPS8 + gid;                  \
            const int i1 = i0 + 4 * MPS8;                                          \
            uint32_t bh0 = mhi_s[i0], bh1 = mhi_s[i1];                             \
            uint32_t bl0 = mlo_s[i0], bl1 = mlo_s[i1];                             \
            _Pragma("unroll")                                                      \
            for (int ct = 0; ct < 4; ct++) {                                       \
                mma_bf16(acc[ct][0], acc[ct][1], acc[ct][2], acc[ct][3],           \
                         Wh[J][ct][0], Wh[J][ct][1], Wh[J][ct][2], Wh[J][ct][3],   \
                         bh0, bh1);                                                \
                mma_bf16(acc[ct][0], acc[ct][1], acc[ct][2], acc[ct][3],           \
                         Wh[J][ct][0], Wh[J][ct][1], Wh[J][ct][2], Wh[J][ct][3],   \
                         bl0, bl1);                                                \
                mma_bf16(acc[ct][0], acc[ct][1], acc[ct][2], acc[ct][3],           \
                         Wl[J][ct][0], Wl[J][ct][1], Wl[J][ct][2], Wl[J][ct][3],   \
                         bh0, bh1);                                                \
            }                                                                      \
        }

        MMA_CHUNK(0, 2)
        MMA_CHUNK(1, 1)
#undef MMA_CHUNK

        // partials -> red[w][cc][12]: d0,d1 = (cc=ct*16+gid, b=2tig,2tig+1); d2,d3 = cc+8
        {
            float* rp = red + w * 768;
#pragma unroll
            for (int ct = 0; ct < 4; ct++) {
                const int cc = ct * 16 + gid;
                *(float2*)&rp[cc * MPS8 + tig * 2]       = make_float2(acc[ct][0], acc[ct][1]);
                *(float2*)&rp[(cc + 8) * MPS8 + tig * 2] = make_float2(acc[ct][2], acc[ct][3]);
            }
        }
        __syncthreads();

        // ---- cell tail (tid<128: 16h x 8b) ----
        float m2 = 0.0f, c2 = 0.0f;
        if (tid < 128) {
            float gate[4];
#pragma unroll
            for (int g = 0; g < 4; g++) {
                const int cc = cj * 4 + g;
                const float* rb = red + cc * MPS8 + cb;
                float sum = xp_s[pb * 512 + cc * GRP_B + cb];
#pragma unroll
                for (int ww = 0; ww < 16; ww++) sum += rb[ww * 768];
                gate[g] = sum;
            }
            float p  = pad_s[pb * 8 + cb];
            float ii = fsig(gate[0]), ff = fsig(gate[1]);
            float gg = ftanh(gate[2]), oo = fsig(gate[3]);
            float cn = ff * c_reg + ii * gg;
            float mn = oo * ftanh(cn);
            m2 = mn + (m_prev - mn) * p;
            c2 = cn + (c_reg - cn) * p;
            c_reg = c2;
            m_prev = m2;

            m2f_s[cj * GRP_B + cb] = m2;

            // pack h-pair via shuffle: tid^8 flips cj bit0
            float m2p = __shfl_xor_sync(0xffffffffu, m2, 8);
            if ((tid & 8) == 0) {      // even cj
                float he = __bfloat162float(__float2bfloat16_rn(m2));
                float ho = __bfloat162float(__float2bfloat16_rn(m2p));
                const int kp = gbid * 8 + (cj >> 1);
                const int gi = ((nb * NGRP + grp) * 256 + kp) * GRP_B + cb;
                g_mP_hi[gi] = pack_bf2(he, ho);
                g_mP_lo[gi] = pack_bf2(m2 - he, m2p - ho);
            }

            asm volatile("bar.sync 1, 128;" ::: "memory");
            // coalesced out: 32 threads: b = tid>>2, hq = tid&3 -> float4
            if (tid < 32) {
                const int b = tid >> 2, hq = tid & 3;
                float4 o4 = make_float4(m2f_s[(hq * 4 + 0) * GRP_B + b],
                                        m2f_s[(hq * 4 + 1) * GRP_B + b],
                                        m2f_s[(hq * 4 + 2) * GRP_B + b],
                                        m2f_s[(hq * 4 + 3) * GRP_B + b]);
                *(float4*)&out[((size_t)s * B_SZ + grp * GRP_B + b) * H_SZ
                               + h_base + hq * 4] = o4;
            }
            if (tid == 0) { __threadfence(); atomicAdd(my_bar, 1); }

            if (write_final && s == T_STEPS - 1) {
                size_t base = (size_t)T_STEPS * B_SZ * H_SZ;
                out[base + (size_t)b_g * H_SZ + h_o] = m2;
                out[base + (size_t)B_SZ * H_SZ + (size_t)b_g * H_SZ + h_o] = c2;
            }
        }

        // ---- per-group grid barrier ----
        if (tid == 0) {
            const int target = GBLK * (s + 1);
            while (*(volatile int*)my_bar < target) { }
            __threadfence();
        }
        __syncthreads();
    }
}

// ---------------- launch ----------------
extern "C" void kernel_launch(void* const* d_in, const int* in_sizes, int n_in,
                              void* d_out, int out_size)
{
    const float* input = (const float*)d_in[0];
    const float* padd  = (const float*)d_in[1];
    const float* W_x   = (const float*)d_in[2];
    const float* W_h   = (const float*)d_in[3];
    const float* bias  = (const float*)d_in[4];
    float* out = (float*)d_out;

    const size_t xp_smem = (size_t)XP_SMEM_FL * sizeof(float);
    cudaFuncSetAttribute(xproj_gemm, cudaFuncAttributeMaxDynamicSharedMemorySize, (int)xp_smem);
    cudaFuncSetAttribute(lstm_kernel, cudaFuncAttributeMaxDynamicSharedMemorySize, SMEM_BYTES_L);

    int write_final =
        ((size_t)out_size >= (size_t)T_STEPS * B_SZ * H_SZ + 2u * B_SZ * H_SZ) ? 1 : 0;

    xproj_gemm<<<dim3(G_SZ / 128, (T_STEPS * B_SZ) / 64), 256, xp_smem>>>(input, W_x, bias);
    lstm_kernel<<<NBLK, 512, SMEM_BYTES_L>>>(padd, W_h, out, write_final);
}

// round 16
// speedup vs baseline: 1.0273x; 1.0273x over previous
#include <cuda_runtime.h>
#include <cuda_bf16.h>
#include <cstdint>

#define T_STEPS 2048
#define B_SZ    32
#define D_SZ    512
#define H_SZ    512
#define G_SZ    2048
#define NBLK    128
#define GRP_B   16      // batch elements per group

// ---------------- device scratch ----------------
__device__ float g_xproj[(size_t)T_STEPS * G_SZ * B_SZ];     // [T][4H][B]
// m packed bf16 pairs per group: P[buf][grp][kp][b16]
__device__ uint32_t g_mP_hi[2 * 2 * 256 * GRP_B];
__device__ uint32_t g_mP_lo[2 * 2 * 256 * GRP_B];
__device__ int g_bars[64];    // counter per group at [grp*32]

// ---------------- helpers ----------------
#define CP_ASYNC16(dst_u32, src_ptr) \
    asm volatile("cp.async.cg.shared.global [%0], [%1], 16;\n" :: "r"(dst_u32), "l"(src_ptr))
#define CP_COMMIT() asm volatile("cp.async.commit_group;\n")
#define CP_WAIT(N)  asm volatile("cp.async.wait_group %0;\n" :: "n"(N))

__device__ __forceinline__ void mma_bf16(float& d0, float& d1, float& d2, float& d3,
                                         uint32_t a0, uint32_t a1, uint32_t a2, uint32_t a3,
                                         uint32_t b0, uint32_t b1) {
    asm volatile(
        "mma.sync.aligned.m16n8k16.row.col.f32.bf16.bf16.f32 "
        "{%0,%1,%2,%3},{%4,%5,%6,%7},{%8,%9},{%0,%1,%2,%3};"
        : "+f"(d0), "+f"(d1), "+f"(d2), "+f"(d3)
        : "r"(a0), "r"(a1), "r"(a2), "r"(a3), "r"(b0), "r"(b1));
}
__device__ __forceinline__ uint32_t pack_bf2(float a, float b) {
    __nv_bfloat162 t = __floats2bfloat162_rn(a, b);
    return *(uint32_t*)&t;
}
__device__ __forceinline__ void split_pair(float f0, float f1, uint32_t& hi, uint32_t& lo) {
    float h0 = __bfloat162float(__float2bfloat16_rn(f0));
    float h1 = __bfloat162float(__float2bfloat16_rn(f1));
    hi = pack_bf2(h0, h1);
    lo = pack_bf2(f0 - h0, f1 - h1);
}

// ============ phase 1: x_proj GEMM (bf16-pair 3-mma k16, 3-stage) ============
#define XPA 2304
#define XPB 4352
#define XP_SMEM_FL (3 * (XPA + XPB))

__global__ __launch_bounds__(256, 2) void xproj_gemm(
    const float* __restrict__ A, const float* __restrict__ Bm,
    const float* __restrict__ bias)
{
    extern __shared__ float sm[];
    float* As = sm;
    float* Bs = sm + 3 * XPA;
    float* stage = Bs;

    const unsigned as_u32 = (unsigned)__cvta_generic_to_shared(As);
    const unsigned bs_u32 = (unsigned)__cvta_generic_to_shared(Bs);

    const int tid = threadIdx.x;

    if (blockIdx.x == 0 && blockIdx.y == 0) {
        for (int i = tid; i < 64; i += 256) g_bars[i] = 0;
        for (int i = tid; i < 2 * 2 * 256 * GRP_B; i += 256) { g_mP_hi[i] = 0u; g_mP_lo[i] = 0u; }
    }

    const int n0 = blockIdx.x * 128;
    const int m0 = blockIdx.y * 64;
    const int w   = tid >> 5;
    const int l   = tid & 31;
    const int gid = l >> 2;
    const int tig = l & 3;
    const int nw  = w * 16;

    auto issue = [&](int it, int buf) {
        const int kc = it * 32;
#pragma unroll
        for (int i = 0; i < 2; i++) {
            int idx = tid + i * 256;
            int m = idx >> 3, kq = (idx & 7) << 2;
            CP_ASYNC16(as_u32 + (unsigned)((buf * XPA + m * 36 + kq) * 4),
                       A + (size_t)(m0 + m) * D_SZ + kc + kq);
        }
#pragma unroll
        for (int i = 0; i < 4; i++) {
            int idx = tid + i * 256;
            int k = idx >> 5, nq = (idx & 31) << 2;
            CP_ASYNC16(bs_u32 + (unsigned)((buf * XPB + k * 136 + nq) * 4),
                       Bm + (size_t)(kc + k) * G_SZ + n0 + nq);
        }
        CP_COMMIT();
    };

    float acc[4][2][4];
#pragma unroll
    for (int mt = 0; mt < 4; mt++)
#pragma unroll
        for (int nt = 0; nt < 2; nt++)
#pragma unroll
            for (int r = 0; r < 4; r++) acc[mt][nt][r] = 0.0f;

    issue(0, 0);
    issue(1, 1);

#pragma unroll 1
    for (int it = 0; it < 16; it++) {
        if (it < 15) { CP_WAIT(1); } else { CP_WAIT(0); }
        __syncthreads();
        if (it + 2 < 16) issue(it + 2, (it + 2) % 3);

        const float* Ab = As + (it % 3) * XPA;
        const float* Bb = Bs + (it % 3) * XPB;

#pragma unroll
        for (int c = 0; c < 2; c++) {
            const int k0 = c * 16 + tig * 2;
            uint32_t bh[2][2], bl[2][2];
#pragma unroll
            for (int nt = 0; nt < 2; nt++) {
                const int n = nw + nt * 8 + gid;
                float b00 = Bb[k0 * 136 + n];
                float b01 = Bb[(k0 + 1) * 136 + n];
                float b10 = Bb[(k0 + 8) * 136 + n];
                float b11 = Bb[(k0 + 9) * 136 + n];
                split_pair(b00, b01, bh[nt][0], bl[nt][0]);
                split_pair(b10, b11, bh[nt][1], bl[nt][1]);
            }
#pragma unroll
            for (int mt = 0; mt < 4; mt++) {
                const int row0 = mt * 16 + gid;
                float2 f0 = *(const float2*)&Ab[row0 * 36 + k0];
                float2 f1 = *(const float2*)&Ab[(row0 + 8) * 36 + k0];
                float2 f2 = *(const float2*)&Ab[row0 * 36 + k0 + 8];
                float2 f3 = *(const float2*)&Ab[(row0 + 8) * 36 + k0 + 8];
                uint32_t ah0, al0, ah1, al1, ah2, al2, ah3, al3;
                split_pair(f0.x, f0.y, ah0, al0);
                split_pair(f1.x, f1.y, ah1, al1);
                split_pair(f2.x, f2.y, ah2, al2);
                split_pair(f3.x, f3.y, ah3, al3);
#pragma unroll
                for (int nt = 0; nt < 2; nt++) {
                    mma_bf16(acc[mt][nt][0], acc[mt][nt][1], acc[mt][nt][2], acc[mt][nt][3],
                             ah0, ah1, ah2, ah3, bh[nt][0], bh[nt][1]);
                    mma_bf16(acc[mt][nt][0], acc[mt][nt][1], acc[mt][nt][2], acc[mt][nt][3],
                             ah0, ah1, ah2, ah3, bl[nt][0], bl[nt][1]);
                    mma_bf16(acc[mt][nt][0], acc[mt][nt][1], acc[mt][nt][2], acc[mt][nt][3],
                             al0, al1, al2, al3, bh[nt][0], bh[nt][1]);
                }
            }
        }
    }
    __syncthreads();

#pragma unroll
    for (int mt = 0; mt < 4; mt++)
#pragma unroll
        for (int nt = 0; nt < 2; nt++) {
            int m = mt * 16 + gid;
            int n = nw + nt * 8 + tig * 2;
            stage[n * 68 + m]           = acc[mt][nt][0];
            stage[(n + 1) * 68 + m]     = acc[mt][nt][1];
            stage[n * 68 + m + 8]       = acc[mt][nt][2];
            stage[(n + 1) * 68 + m + 8] = acc[mt][nt][3];
        }
    __syncthreads();

#pragma unroll
    for (int i = 0; i < 8; i++) {
        int idx = tid + i * 256;
        int n = idx >> 4, mq = (idx & 15) << 2;
        float4 v = *(float4*)&stage[n * 68 + mq];
        float bb = bias[n0 + n];
        v.x += bb; v.y += bb; v.z += bb; v.w += bb;
        int mg = m0 + mq;
        int t = mg >> 5, b = mg & 31;
        *(float4*)&g_xproj[((size_t)t * G_SZ + n0 + n) * B_SZ + b] = v;
    }
}

// ============ phase 2: two 64-block group recurrences, K-split 8 x 2 ========
// grp = bid>>6 owns b [grp*16,+16); block owns 8 h (32 cc).
// warp = (wk = w&7 K-split, grpN = w>>3 covers cc [grpN*16, +16)).
#define MPS16 24                                   // u32 stride per kp row
#define MHI_OFF_B 0                                // 256*24*4 = 24576
#define MLO_OFF_B 24576
#define RED_OFF_B 49152                            // [8 wk][32cc][20] f32 = 20480
#define XP_OFF_B  69632                            // [2][32cc][16b] f32 = 4096
#define PAD_OFF_B 73728                            // [2][16] f32 = 128
#define M2F_OFF_B 73856                            // [8][16] f32 = 512
#define SMEM_BYTES_L 74368

__device__ __forceinline__ float fsig(float x)  { return 1.0f / (1.0f + __expf(-x)); }
__device__ __forceinline__ float ftanh(float x) { return 1.0f - 2.0f / (__expf(2.0f * x) + 1.0f); }

__global__ __launch_bounds__(512, 1) void lstm_kernel(
    const float* __restrict__ paddings,
    const float* __restrict__ W_h,
    float* __restrict__ out,
    int write_final)
{
    extern __shared__ char smc[];
    const uint32_t* mhi_s = (const uint32_t*)(smc + MHI_OFF_B);
    const uint32_t* mlo_s = (const uint32_t*)(smc + MLO_OFF_B);
    float* red   = (float*)(smc + RED_OFF_B);
    float* xp_s  = (float*)(smc + XP_OFF_B);
    float* pad_s = (float*)(smc + PAD_OFF_B);
    float* m2f_s = (float*)(smc + M2F_OFF_B);

    const unsigned smem_u32 = (unsigned)__cvta_generic_to_shared(smc);
    const unsigned mhi_u32  = smem_u32 + MHI_OFF_B;
    const unsigned mlo_u32  = smem_u32 + MLO_OFF_B;
    const unsigned xp_u32   = smem_u32 + XP_OFF_B;
    const unsigned pad_u32  = smem_u32 + PAD_OFF_B;

    const int tid  = threadIdx.x;
    const int bid  = blockIdx.x;
    const int grp  = bid >> 6;
    const int gbid = bid & 63;
    const int h_base = gbid * 8;

    const int l    = tid & 31;
    const int w    = tid >> 5;
    const int wk   = w & 7;       // K-split index
    const int grpN = w >> 3;      // cc half
    const int gid  = l >> 2;
    const int tig  = l & 3;

    // ---- W fragments (bf16 pairs): 16 cc per warp = 2 n-tiles, 4 K-chunks ----
    uint32_t Wh[4][2][2], Wl[4][2][2];
#pragma unroll
    for (int J = 0; J < 4; J++)
#pragma unroll
        for (int nt = 0; nt < 2; nt++)
#pragma unroll
            for (int r = 0; r < 2; r++) {
                int k  = wk * 64 + J * 16 + tig * 2 + r * 8;
                int cc = grpN * 16 + nt * 8 + gid;
                int g  = cc & 3;
                int j8 = cc >> 2;              // 0..7
                const float* wp = W_h + (size_t)g * H_SZ + h_base + j8;
                float w0 = wp[(size_t)k * G_SZ];
                float w1 = wp[(size_t)(k + 1) * G_SZ];
                split_pair(w0, w1, Wh[J][nt][r], Wl[J][nt][r]);
            }

    // cell ownership (tid<128): cb = tid&15, cj = tid>>4 (0..7)
    const int cb  = tid & 15;
    const int cj  = tid >> 4;
    const int h_o = h_base + cj;
    const int b_g = grp * GRP_B + cb;

    // xp loader coords (tid<128): 32cc x 16b, 16B granules
    const int xcc = tid >> 2;
    const int xq  = (tid & 3) << 2;
    const float* xp_src_base = g_xproj +
        ((size_t)((xcc & 3) * H_SZ + h_base + (xcc >> 2))) * B_SZ + grp * GRP_B + xq;

    // m loader coords: per chunk kp rows [wk*32 + J*8, +8); lane row l>>2, 16B piece l&3
    const int mrow = l >> 2;
    const int mq16 = (l & 3) * 16;

    // prologue: xp(0) + pad(0)
    if (tid < 128)
        CP_ASYNC16(xp_u32 + (unsigned)((xcc * GRP_B + xq) * 4), xp_src_base);
    if (tid >= 128 && tid < 132)
        CP_ASYNC16(pad_u32 + (unsigned)((tid - 128) * 16),
                   paddings + grp * GRP_B + (tid - 128) * 4);
    CP_COMMIT();

    float c_reg = 0.0f, m_prev = 0.0f;
    int* my_bar = &g_bars[grp * 32];

#pragma unroll 1
    for (int s = 0; s < T_STEPS; s++) {
        const int pb = s & 1, nb = pb ^ 1;
        const char* srcP_hi = (const char*)(g_mP_hi + (pb * 2 + grp) * 256 * GRP_B);
        const char* srcP_lo = (const char*)(g_mP_lo + (pb * 2 + grp) * 256 * GRP_B);

        // ---- 4 warp-private m groups (one per k16 chunk) ----
#pragma unroll
        for (int J = 0; J < 4; J++) {
            const int kp = wk * 32 + J * 8 + mrow;
            const unsigned sb = (unsigned)(kp * 64 + mq16);
            const unsigned db = (unsigned)(kp * (MPS16 * 4) + mq16);
            CP_ASYNC16(mhi_u32 + db, srcP_hi + sb);
            CP_ASYNC16(mlo_u32 + db, srcP_lo + sb);
            CP_COMMIT();
        }
        // ---- xp(s+1)+pad(s+1) prefetch ----
        if (s + 1 < T_STEPS) {
            if (tid < 128)
                CP_ASYNC16(xp_u32 + (unsigned)(((nb * 512) + xcc * GRP_B + xq) * 4),
                           xp_src_base + (size_t)(s + 1) * G_SZ * B_SZ);
            if (tid >= 128 && tid < 132)
                CP_ASYNC16(pad_u32 + (unsigned)((nb * 16 + (tid - 128) * 4) * 4),
                           paddings + (size_t)(s + 1) * B_SZ + grp * GRP_B + (tid - 128) * 4);
        }
        CP_COMMIT();

        float acc1[2][4], acc2[2][4];
#pragma unroll
        for (int nt = 0; nt < 2; nt++)
#pragma unroll
            for (int r = 0; r < 4; r++) { acc1[nt][r] = 0.0f; acc2[nt][r] = 0.0f; }

        // ---- 4 mma chunks (M=16 batch, N=16 cc), warp-paced ----
#define MMA_CHUNK(J, WN)                                                           \
        {                                                                          \
            CP_WAIT(WN);                                                           \
            __syncwarp();                                                          \
            const int i0 = (wk * 32 + (J) * 8 + tig) * MPS16 + gid;                \
            const int i2 = i0 + 4 * MPS16;                                         \
            uint32_t ah0 = mhi_s[i0], ah1 = mhi_s[i0 + 8];                         \
            uint32_t ah2 = mhi_s[i2], ah3 = mhi_s[i2 + 8];                         \
            uint32_t al0 = mlo_s[i0], al1 = mlo_s[i0 + 8];                         \
            uint32_t al2 = mlo_s[i2], al3 = mlo_s[i2 + 8];                         \
            _Pragma("unroll")                                                      \
            for (int nt = 0; nt < 2; nt++) {                                       \
                mma_bf16(acc1[nt][0], acc1[nt][1], acc1[nt][2], acc1[nt][3],       \
                         ah0, ah1, ah2, ah3, Wh[J][nt][0], Wh[J][nt][1]);          \
                mma_bf16(acc2[nt][0], acc2[nt][1], acc2[nt][2], acc2[nt][3],       \
                         ah0, ah1, ah2, ah3, Wl[J][nt][0], Wl[J][nt][1]);          \
                mma_bf16(acc2[nt][0], acc2[nt][1], acc2[nt][2], acc2[nt][3],       \
                         al0, al1, al2, al3, Wh[J][nt][0], Wh[J][nt][1]);          \
            }                                                                      \
        }

        MMA_CHUNK(0, 4)
        MMA_CHUNK(1, 3)
        MMA_CHUNK(2, 2)
        MMA_CHUNK(3, 1)
#undef MMA_CHUNK

        // partials -> red[wk][cc][20]
        {
            float* rp = red + wk * 640;
#pragma unroll
            for (int nt = 0; nt < 2; nt++) {
                const int cc = grpN * 16 + nt * 8 + tig * 2;
                rp[cc * 20 + gid]           = acc1[nt][0] + acc2[nt][0];
                rp[(cc + 1) * 20 + gid]     = acc1[nt][1] + acc2[nt][1];
                rp[cc * 20 + gid + 8]       = acc1[nt][2] + acc2[nt][2];
                rp[(cc + 1) * 20 + gid + 8] = acc1[nt][3] + acc2[nt][3];
            }
        }
        __syncthreads();

        // ---- cell tail (tid<128: 8h x 16b), 8-deep reduction ----
        float m2 = 0.0f, c2 = 0.0f;
        if (tid < 128) {
            float gate[4];
#pragma unroll
            for (int g = 0; g < 4; g++) {
                const int cc = cj * 4 + g;
                const float* rb = red + cc * 20 + cb;
                float sum = xp_s[pb * 512 + cc * GRP_B + cb];
#pragma unroll
                for (int ww = 0; ww < 8; ww++) sum += rb[ww * 640];
                gate[g] = sum;
            }
            float p  = pad_s[pb * 16 + cb];
            float ii = fsig(gate[0]), ff = fsig(gate[1]);
            float gg = ftanh(gate[2]), oo = fsig(gate[3]);
            float cn = ff * c_reg + ii * gg;
            float mn = oo * ftanh(cn);
            m2 = mn + (m_prev - mn) * p;
            c2 = cn + (c_reg - cn) * p;
            c_reg = c2;
            m_prev = m2;

            m2f_s[cj * GRP_B + cb] = m2;

            // pack h-pair via shuffle: lanes l and l^16 hold (even cj, odd cj)
            float m2p = __shfl_xor_sync(0xffffffffu, m2, 16);
            if ((tid & 16) == 0) {
                float he = __bfloat162float(__float2bfloat16_rn(m2));
                float ho = __bfloat162float(__float2bfloat16_rn(m2p));
                const int kp = gbid * 4 + w;        // w = tid>>5 in 0..3 here
                const int gi = ((nb * 2 + grp) * 256 + kp) * GRP_B + cb;
                g_mP_hi[gi] = pack_bf2(he, ho);
                g_mP_lo[gi] = pack_bf2(m2 - he, m2p - ho);
            }

            asm volatile("bar.sync 1, 128;" ::: "memory");
            if (tid < 32) {
                const int b = tid >> 1, half = tid & 1;
                float4 o4 = make_float4(m2f_s[(half * 4 + 0) * GRP_B + b],
                                        m2f_s[(half * 4 + 1) * GRP_B + b],
                                        m2f_s[(half * 4 + 2) * GRP_B + b],
                                        m2f_s[(half * 4 + 3) * GRP_B + b]);
                *(float4*)&out[((size_t)s * B_SZ + grp * GRP_B + b) * H_SZ
                               + h_base + half * 4] = o4;
            }
            if (tid == 0) { __threadfence(); atomicAdd(my_bar, 1); }

            if (write_final && s == T_STEPS - 1) {
                size_t base = (size_t)T_STEPS * B_SZ * H_SZ;
                out[base + (size_t)b_g * H_SZ + h_o] = m2;
                out[base + (size_t)B_SZ * H_SZ + (size_t)b_g * H_SZ + h_o] = c2;
            }
        }

        // ---- per-group grid barrier ----
        if (tid == 0) {
            const int target = 64 * (s + 1);
            while (*(volatile int*)my_bar < target) { }
            __threadfence();
        }
        __syncthreads();
    }
}

// ---------------- launch ----------------
extern "C" void kernel_launch(void* const* d_in, const int* in_sizes, int n_in,
                              void* d_out, int out_size)
{
    const float* input = (const float*)d_in[0];
    const float* padd  = (const float*)d_in[1];
    const float* W_x   = (const float*)d_in[2];
    const float* W_h   = (const float*)d_in[3];
    const float* bias  = (const float*)d_in[4];
    float* out = (float*)d_out;

    const size_t xp_smem = (size_t)XP_SMEM_FL * sizeof(float);
    cudaFuncSetAttribute(xproj_gemm, cudaFuncAttributeMaxDynamicSharedMemorySize, (int)xp_smem);
    cudaFuncSetAttribute(lstm_kernel, cudaFuncAttributeMaxDynamicSharedMemorySize, SMEM_BYTES_L);

    int write_final =
        ((size_t)out_size >= (size_t)T_STEPS * B_SZ * H_SZ + 2u * B_SZ * H_SZ) ? 1 : 0;

    xproj_gemm<<<dim3(G_SZ / 128, (T_STEPS * B_SZ) / 64), 256, xp_smem>>>(input, W_x, bias);
    lstm_kernel<<<NBLK, 512, SMEM_BYTES_L>>>(padd, W_h, out, write_final);
}